// round 6
// baseline (speedup 1.0000x reference)
#include <cuda_runtime.h>
#include <cstdint>

#define NB 64
#define NT 4096
#define NS 64

__device__ __forceinline__ void fma2(unsigned long long &d, unsigned long long a, unsigned long long b) {
    asm("fma.rn.f32x2 %0, %1, %2, %0;" : "+l"(d) : "l"(a), "l"(b));
}
__device__ __forceinline__ unsigned long long add2(unsigned long long a, unsigned long long b) {
    unsigned long long d;
    asm("add.rn.f32x2 %0, %1, %2;" : "=l"(d) : "l"(a), "l"(b));
    return d;
}
__device__ __forceinline__ unsigned long long pk2(float lo, float hi) {
    unsigned long long d;
    asm("mov.b64 %0, {%1, %2};" : "=l"(d) : "f"(lo), "f"(hi));
    return d;
}

__global__ __launch_bounds__(NS, 1) void hmm_forward_kernel(
    const float* __restrict__ trans,   // (S,S)
    const float* __restrict__ emis,    // (B,T,S)
    float* __restrict__ alpha_out,     // (B,T,S)
    float* __restrict__ logz_out)      // (B,)
{
    const int b = blockIdx.x;
    const int j = threadIdx.x;      // state index 0..63

    __shared__ __align__(16) float sv[2][NS];   // exp(alpha_prev - m), double buffered
    __shared__ float sm0[2];                    // alpha[0] broadcast (stale normalizer)

    // --- Load exp(transition) column j into packed f32x2 register pairs ---
    // eA[k] = (exp(A[2k][j]), exp(A[2k+1][j]))
    unsigned long long eA[NS / 2];
#pragma unroll
    for (int k = 0; k < NS / 2; k++) {
        float e0 = __expf(trans[(2 * k) * NS + j]);
        float e1 = __expf(trans[(2 * k + 1) * NS + j]);
        eA[k] = pk2(e0, e1);
    }

    const float* eb = emis + (size_t)b * NT * NS;
    float* ob = alpha_out + (size_t)b * NT * NS;

    // --- t = 0 ---
    float a = eb[j];
    ob[j] = a;
    if (j == 0) sm0[0] = a;

    // Prefetch emissions for t = 1..4
    float ebuf[4];
#pragma unroll
    for (int p = 0; p < 4; p++) ebuf[p] = eb[(size_t)(1 + p) * NS + j];

    __syncthreads();
    float m = sm0[0];

    // --- Main sequential recurrence ---
#pragma unroll 4
    for (int t = 1; t < NT; t++) {
        const int buf = t & 1;
        // v_j = exp(alpha_{t-1}[j] - m); m is a ~2-step-stale uniform normalizer
        float v = __expf(a - m);
        sv[buf][j] = v;
        if (j == 0) sm0[buf] = a;     // publish alpha_{t-1}[0] for future m
        __syncthreads();
        float m_next = sm0[buf];      // = alpha_{t-1}[0]

        // w_j = sum_i v_i * expA[i][j], packed f32x2 across (even i, odd i)
        const float4* svv = reinterpret_cast<const float4*>(&sv[buf][0]);
        unsigned long long acc0 = 0ull, acc1 = 0ull, acc2 = 0ull, acc3 = 0ull;
#pragma unroll
        for (int k = 0; k < 8; k++) {
            float4 q0 = svv[2 * k];
            float4 q1 = svv[2 * k + 1];
            fma2(acc0, pk2(q0.x, q0.y), eA[4 * k + 0]);
            fma2(acc1, pk2(q0.z, q0.w), eA[4 * k + 1]);
            fma2(acc2, pk2(q1.x, q1.y), eA[4 * k + 2]);
            fma2(acc3, pk2(q1.z, q1.w), eA[4 * k + 3]);
        }
        unsigned long long s = add2(add2(acc0, acc1), add2(acc2, acc3));
        float lo, hi;
        asm("mov.b64 {%0, %1}, %2;" : "=f"(lo), "=f"(hi) : "l"(s));
        float w = lo + hi;

        float e_cur = ebuf[(t - 1) & 3];
        float anew = __logf(w) + m + e_cur;
        ob[(size_t)t * NS + j] = anew;

        // refill prefetch slot with e[t+4]
        ebuf[(t - 1) & 3] = (t + 4 < NT) ? eb[(size_t)(t + 4) * NS + j] : 0.0f;

        a = anew;
        m = m_next;
    }

    // --- log_Z = logsumexp over final alpha ---
    float sfin = __expf(a - m);
    sv[0][j] = sfin;
    __syncthreads();
    if (j == 0) {
        float tot = 0.0f;
#pragma unroll
        for (int i = 0; i < NS; i++) tot += sv[0][i];
        logz_out[b] = m + __logf(tot);
    }
}

extern "C" void kernel_launch(void* const* d_in, const int* in_sizes, int n_in,
                              void* d_out, int out_size) {
    const float* trans = (const float*)d_in[0];  // (S,S) fp32
    const float* emis  = (const float*)d_in[1];  // (B,T,S) fp32
    // d_in[2] = seq_lens (unused by reference)
    float* alpha = (float*)d_out;                       // (B,T,S)
    float* logz  = alpha + (size_t)NB * NT * NS;        // (B,)
    hmm_forward_kernel<<<NB, NS>>>(trans, emis, alpha, logz);
}